// round 10
// baseline (speedup 1.0000x reference)
#include <cuda_runtime.h>
#include <cuda_fp16.h>
#include <cstdint>

#define N_NODES 100000
#define D 128
#define E_EDGES 640000

#define MTILE 128
#define NBLK 782                 // 782 * 128 = 100096
#define NSM 148

#define CAP 40                   // in-degree capacity (Poisson(6.4): P(>40)~1e-12)
#define OVF_MAX 4096

// ---- MMA smem tile layout (row stride 272B keeps ldmatrix conflict-free) ----
#define RB 272
#define T_BYTES (128 * RB)          // 34816 per tile

__device__ int   g_cnt[N_NODES];
__device__ int   g_list[(size_t)N_NODES * CAP];
__device__ int   g_ovf_cnt;
__device__ int2  g_ovf[OVF_MAX];
__device__ __align__(16) __half g_xh[(size_t)N_NODES * D];     // fp16 copy of x
__device__ __align__(16) uint8_t g_Wprep[2 * T_BYTES];  // fp16 W1,W2 pre-swizzled

// smem: single A tile + W1 + W2 + biases
#define SM_A   0
#define SM_W1  (T_BYTES)
#define SM_W2  (2 * T_BYTES)
#define SM_B1  (3 * T_BYTES)
#define SM_B2  (3 * T_BYTES + 512)
#define SM_TOTAL (3 * T_BYTES + 1024)   // 105472

#define MLP_T 512                       // 16 warps, warp tile 32x32

// ---------------------------------------------------------------------------
// helpers
// ---------------------------------------------------------------------------
__device__ __forceinline__ uint32_t smem_u32(const void* p) {
    uint32_t a;
    asm("{ .reg .u64 t; cvta.to.shared.u64 t, %1; cvt.u32.u64 %0, t; }"
        : "=r"(a) : "l"(p));
    return a;
}
#define CP_ASYNC16(saddr, gptr) \
    asm volatile("cp.async.cg.shared.global [%0], [%1], 16;" \
        :: "r"(saddr), "l"(gptr) : "memory")
#define CP_COMMIT() asm volatile("cp.async.commit_group;" ::: "memory")
#define CP_WAIT0()  asm volatile("cp.async.wait_group 0;" ::: "memory")

#define LDSM_X4(r0, r1, r2, r3, addr) \
    asm volatile("ldmatrix.sync.aligned.m8n8.x4.shared.b16 {%0,%1,%2,%3}, [%4];" \
        : "=r"(r0), "=r"(r1), "=r"(r2), "=r"(r3) : "r"(addr))

__device__ __forceinline__ void mma_f16(float* d, const uint32_t* a, const uint32_t* b) {
    asm volatile(
        "mma.sync.aligned.m16n8k16.row.col.f32.f16.f16.f32 "
        "{%0,%1,%2,%3}, {%4,%5,%6,%7}, {%8,%9}, {%0,%1,%2,%3};"
        : "+f"(d[0]), "+f"(d[1]), "+f"(d[2]), "+f"(d[3])
        : "r"(a[0]), "r"(a[1]), "r"(a[2]), "r"(a[3]), "r"(b[0]), "r"(b[1]));
}
__device__ __forceinline__ uint32_t packh2(float a, float b) {
    __half2 p = __floats2half2_rn(a, b);
    return *(uint32_t*)&p;
}
__device__ __forceinline__ void addh2(float& a, float& b, uint32_t p) {
    float2 f = __half22float2(*(__half2*)&p);
    a += f.x; b += f.y;
}

// ---------------------------------------------------------------------------
// Kernel A: zero counters + W prep + x -> fp16 conversion
// ---------------------------------------------------------------------------
__global__ void prep_kernel(const float* __restrict__ x,
                            const float* __restrict__ W1,
                            const float* __restrict__ W2) {
    int i = blockIdx.x * blockDim.x + threadIdx.x;
    if (i < N_NODES * 32) {                // x: one float4 -> uint2 (4 halves)
        float4 v = ((const float4*)x)[i];
        uint2 p;
        p.x = packh2(v.x, v.y);
        p.y = packh2(v.z, v.w);
        ((uint2*)g_xh)[i] = p;
    }
    if (i < N_NODES / 4) ((int4*)g_cnt)[i] = make_int4(0, 0, 0, 0);
    if (i == 0) g_ovf_cnt = 0;
    if (i < D * D) {
        int k = i >> 7, n = i & 127;
        uint32_t so = (uint32_t)(n * RB + (k >> 3) * 16 + (k & 7) * 2);
        *(__half*)(g_Wprep + so)           = __float2half_rn(W1[i]);
        *(__half*)(g_Wprep + T_BYTES + so) = __float2half_rn(W2[i]);
    }
}

// ---------------------------------------------------------------------------
// Kernel B: bucket edges by destination (2 edges per thread)
// ---------------------------------------------------------------------------
__global__ void place_kernel(const int* __restrict__ ei) {
    int t = blockIdx.x * blockDim.x + threadIdx.x;
    #pragma unroll
    for (int u = 0; u < 2; u++) {
        int e = t * 2 + u;
        if (e >= E_EDGES) return;
        int r = ei[e];              // source
        int c = ei[E_EDGES + e];    // destination
        int p = atomicAdd(&g_cnt[c], 1);
        if (p < CAP) {
            g_list[(size_t)c * CAP + p] = r;
        } else {
            int q = atomicAdd(&g_ovf_cnt, 1);
            if (q < OVF_MAX) g_ovf[q] = make_int2(r, c);
        }
    }
}

// ---------------------------------------------------------------------------
// Fused kernel: persistent gather + MLP.
// Per tile: 16 warps each gather 8 nodes (H = x + sum x[src]) straight into
// the swizzled smem A tile, then GEMM1 -> relu epilogue -> GEMM2 -> out.
// ---------------------------------------------------------------------------
__device__ __forceinline__ void warp_gemm(
    uint32_t sb, uint32_t a_t, uint32_t w_t,
    int m0, int n0, int lane, float acc[2][4][4])
{
    const int li = lane & 7;
    const int sub = lane >> 3;
    const uint32_t a_off = (uint32_t)((li + (sub & 1) * 8) * RB + (sub >> 1) * 16);
    const uint32_t b_off = (uint32_t)((li + (sub >> 1) * 8) * RB + (sub & 1) * 16);

    #pragma unroll
    for (int ks = 0; ks < 8; ks++) {
        const uint32_t kchunk = (uint32_t)(ks * 32);
        uint32_t ah[2][4];
        #pragma unroll
        for (int mi = 0; mi < 2; mi++) {
            uint32_t base = (uint32_t)((m0 + mi * 16) * RB) + a_off + kchunk;
            LDSM_X4(ah[mi][0], ah[mi][1], ah[mi][2], ah[mi][3], sb + a_t + base);
        }
        uint32_t bh[4][2];
        #pragma unroll
        for (int nj = 0; nj < 2; nj++) {
            uint32_t base = (uint32_t)((n0 + nj * 16) * RB) + b_off + kchunk;
            uint32_t r0, r1, r2, r3;
            LDSM_X4(r0, r1, r2, r3, sb + w_t + base);
            bh[nj * 2][0] = r0; bh[nj * 2][1] = r1;
            bh[nj * 2 + 1][0] = r2; bh[nj * 2 + 1][1] = r3;
        }
        #pragma unroll
        for (int mi = 0; mi < 2; mi++)
            #pragma unroll
            for (int ni = 0; ni < 4; ni++)
                mma_f16(acc[mi][ni], ah[mi], bh[ni]);
    }
}

__global__ void __launch_bounds__(MLP_T, 1)
fused_kernel(const float* __restrict__ b1, const float* __restrict__ b2,
             float* __restrict__ out) {
    extern __shared__ char smem[];
    const uint32_t sb = smem_u32(smem);
    const int tid = threadIdx.x;
    const int lane = tid & 31;
    const int wid = tid >> 5;
    const int m0 = (wid & 3) * 32;     // 4 m-tiles
    const int n0 = (wid >> 2) * 32;    // 4 n-tiles

    if (tid < 128) {
        ((float*)(smem + SM_B1))[tid] = b1[tid];
        ((float*)(smem + SM_B2))[tid] = b2[tid];
    }
    // stage W tiles once via cp.async
    {
        const char* wg = (const char*)g_Wprep;
        #pragma unroll 4
        for (int i = tid; i < 2 * T_BYTES / 16; i += MLP_T)
            CP_ASYNC16(sb + SM_W1 + i * 16, wg + i * 16);
    }
    CP_COMMIT();
    CP_WAIT0();

    const uint2* xr = (const uint2*)g_xh;    // 32 uint2 per row

    for (int t = blockIdx.x; t < NBLK; t += NSM) {
        // ---- gather phase: warp w gathers nodes t*128 + w*8 .. +7 ----
        #pragma unroll 1
        for (int j = 0; j < 8; j++) {
            int row = wid * 8 + j;
            int g = t * MTILE + row;
            if (g >= N_NODES) break;
            int cnt0 = g_cnt[g];
            int cnt = cnt0 > CAP ? CAP : cnt0;

            uint2 own = __ldg(&xr[(size_t)g * 32 + lane]);
            float ax0 = 0.f, ay0 = 0.f, az0 = 0.f, aw0 = 0.f;
            float ax1 = 0.f, ay1 = 0.f, az1 = 0.f, aw1 = 0.f;
            float ax2 = 0.f, ay2 = 0.f, az2 = 0.f, aw2 = 0.f;
            float ax3 = 0.f, ay3 = 0.f, az3 = 0.f, aw3 = 0.f;
            addh2(ax0, ay0, own.x); addh2(az0, aw0, own.y);

            int mysrc = (lane < cnt) ? g_list[(size_t)g * CAP + lane] : 0;
            int c2 = cnt < 32 ? cnt : 32;
            int i = 0;
            for (; i + 4 <= c2; i += 4) {
                int s0 = __shfl_sync(0xffffffffu, mysrc, i);
                int s1 = __shfl_sync(0xffffffffu, mysrc, i + 1);
                int s2 = __shfl_sync(0xffffffffu, mysrc, i + 2);
                int s3 = __shfl_sync(0xffffffffu, mysrc, i + 3);
                uint2 v0 = __ldg(&xr[(size_t)s0 * 32 + lane]);
                uint2 v1 = __ldg(&xr[(size_t)s1 * 32 + lane]);
                uint2 v2 = __ldg(&xr[(size_t)s2 * 32 + lane]);
                uint2 v3 = __ldg(&xr[(size_t)s3 * 32 + lane]);
                addh2(ax0, ay0, v0.x); addh2(az0, aw0, v0.y);
                addh2(ax1, ay1, v1.x); addh2(az1, aw1, v1.y);
                addh2(ax2, ay2, v2.x); addh2(az2, aw2, v2.y);
                addh2(ax3, ay3, v3.x); addh2(az3, aw3, v3.y);
            }
            for (; i < c2; i++) {
                int s = __shfl_sync(0xffffffffu, mysrc, i);
                uint2 v = __ldg(&xr[(size_t)s * 32 + lane]);
                addh2(ax0, ay0, v.x); addh2(az0, aw0, v.y);
            }
            for (int q = 32; q < cnt; q++) {                    // rare
                int s = g_list[(size_t)g * CAP + q];
                uint2 v = __ldg(&xr[(size_t)s * 32 + lane]);
                addh2(ax0, ay0, v.x); addh2(az0, aw0, v.y);
            }
            if (cnt0 > CAP) {                                   // ultra-rare
                int n = g_ovf_cnt; if (n > OVF_MAX) n = OVF_MAX;
                for (int e = 0; e < n; e++) {
                    int2 ed = g_ovf[e];
                    if (ed.y == g) {
                        uint2 v = __ldg(&xr[(size_t)ed.x * 32 + lane]);
                        addh2(ax0, ay0, v.x); addh2(az0, aw0, v.y);
                    }
                }
            }
            float fx = (ax0 + ax1) + (ax2 + ax3);
            float fy = (ay0 + ay1) + (ay2 + ay3);
            float fz = (az0 + az1) + (az2 + az3);
            float fw = (aw0 + aw1) + (aw2 + aw3);

            uint32_t so = (uint32_t)(row * RB + (lane >> 1) * 16 + (lane & 1) * 8);
            uint2 p;
            p.x = packh2(fx, fy);
            p.y = packh2(fz, fw);
            *(uint2*)(smem + SM_A + so) = p;
        }
        __syncthreads();

        float acc[2][4][4];

        // GEMM1: H1 = relu(A @ W1 + b1)
        #pragma unroll
        for (int mi = 0; mi < 2; mi++)
            #pragma unroll
            for (int ni = 0; ni < 4; ni++)
                #pragma unroll
                for (int q = 0; q < 4; q++) acc[mi][ni][q] = 0.0f;

        warp_gemm(sb, SM_A, SM_W1, m0, n0, lane, acc);
        __syncthreads();

        {
            const float* b1s = (const float*)(smem + SM_B1);
            #pragma unroll
            for (int mi = 0; mi < 2; mi++) {
                int r0 = m0 + mi * 16 + (lane >> 2);
                #pragma unroll
                for (int ni = 0; ni < 4; ni++) {
                    int c0 = n0 + ni * 8 + (lane & 3) * 2;
                    float bb0 = b1s[c0], bb1 = b1s[c0 + 1];
                    float v00 = fmaxf(acc[mi][ni][0] + bb0, 0.0f);
                    float v01 = fmaxf(acc[mi][ni][1] + bb1, 0.0f);
                    float v10 = fmaxf(acc[mi][ni][2] + bb0, 0.0f);
                    float v11 = fmaxf(acc[mi][ni][3] + bb1, 0.0f);
                    uint32_t so0 = (uint32_t)(r0 * RB + (c0 >> 3) * 16 + (c0 & 7) * 2);
                    uint32_t so1 = so0 + 8 * RB;
                    *(uint32_t*)(smem + SM_A + so0) = packh2(v00, v01);
                    *(uint32_t*)(smem + SM_A + so1) = packh2(v10, v11);
                }
            }
        }
        __syncthreads();

        // GEMM2: out = H1 @ W2 + b2
        #pragma unroll
        for (int mi = 0; mi < 2; mi++)
            #pragma unroll
            for (int ni = 0; ni < 4; ni++)
                #pragma unroll
                for (int q = 0; q < 4; q++) acc[mi][ni][q] = 0.0f;

        warp_gemm(sb, SM_A, SM_W2, m0, n0, lane, acc);

        {
            const float* b2s = (const float*)(smem + SM_B2);
            int base_m = t * MTILE + m0;
            #pragma unroll
            for (int mi = 0; mi < 2; mi++) {
                int gr0 = base_m + mi * 16 + (lane >> 2);
                int gr1 = gr0 + 8;
                #pragma unroll
                for (int ni = 0; ni < 4; ni++) {
                    int c0 = n0 + ni * 8 + (lane & 3) * 2;
                    float bb0 = b2s[c0], bb1 = b2s[c0 + 1];
                    if (gr0 < N_NODES) {
                        float2 v = make_float2(acc[mi][ni][0] + bb0, acc[mi][ni][1] + bb1);
                        *(float2*)(out + (size_t)gr0 * D + c0) = v;
                    }
                    if (gr1 < N_NODES) {
                        float2 v = make_float2(acc[mi][ni][2] + bb0, acc[mi][ni][3] + bb1);
                        *(float2*)(out + (size_t)gr1 * D + c0) = v;
                    }
                }
            }
        }
        __syncthreads();    // A reused by next tile's gather
    }
}

// ---------------------------------------------------------------------------
extern "C" void kernel_launch(void* const* d_in, const int* in_sizes, int n_in,
                              void* d_out, int out_size) {
    const float* x  = (const float*)d_in[0];
    const int*   ei = (const int*)d_in[1];
    const float* W1 = (const float*)d_in[2];
    const float* b1 = (const float*)d_in[3];
    const float* W2 = (const float*)d_in[4];
    const float* b2 = (const float*)d_in[5];
    float*       out = (float*)d_out;

    prep_kernel<<<(N_NODES * 32 + 255) / 256, 256>>>(x, W1, W2);
    place_kernel<<<(E_EDGES / 2 + 255) / 256, 256>>>(ei);
    {
        cudaFuncSetAttribute(fused_kernel,
                             cudaFuncAttributeMaxDynamicSharedMemorySize, SM_TOTAL);
        fused_kernel<<<NSM, MLP_T, SM_TOTAL>>>(b1, b2, out);
    }
}

// round 11
// speedup vs baseline: 1.4144x; 1.4144x over previous
#include <cuda_runtime.h>
#include <cuda_fp16.h>
#include <cstdint>

#define N_NODES 100000
#define D 128
#define E_EDGES 640000

#define MTILE 128
#define NBLK 782                 // 782 * 128 = 100096
#define NSM 148

#define CAP 40                   // in-degree capacity (Poisson(6.4): P(>40)~1e-12)
#define OVF_MAX 4096

// ---- MMA smem tile layout (row stride 272B keeps ldmatrix conflict-free) ----
#define RB 272
#define T_BYTES (128 * RB)          // 34816 per tile

__device__ int   g_cnt[N_NODES];
__device__ int   g_list[(size_t)N_NODES * CAP];
__device__ int   g_ovf_cnt;
__device__ int2  g_ovf[OVF_MAX];
__device__ __align__(16) __half g_xh[(size_t)N_NODES * D];     // fp16 copy of x
// H in fp16, pre-swizzled MMA layout, one T_BYTES block per 128-row tile
__device__ __align__(16) uint8_t g_Hh[(size_t)NBLK * T_BYTES];
__device__ __align__(16) uint8_t g_Wprep[2 * T_BYTES];  // fp16 W1,W2 pre-swizzled

// smem: A double buffer + W1 + W2 + biases
#define SM_A0  0
#define SM_A1  (T_BYTES)
#define SM_W1  (2 * T_BYTES)
#define SM_W2  (3 * T_BYTES)
#define SM_B1  (4 * T_BYTES)
#define SM_B2  (4 * T_BYTES + 512)
#define SM_TOTAL (4 * T_BYTES + 1024)   // 140288

#define MLP_T 512                       // 16 warps, warp tile 32x32

// ---------------------------------------------------------------------------
// helpers
// ---------------------------------------------------------------------------
__device__ __forceinline__ uint32_t smem_u32(const void* p) {
    uint32_t a;
    asm("{ .reg .u64 t; cvta.to.shared.u64 t, %1; cvt.u32.u64 %0, t; }"
        : "=r"(a) : "l"(p));
    return a;
}
#define CP_ASYNC16(saddr, gptr) \
    asm volatile("cp.async.cg.shared.global [%0], [%1], 16;" \
        :: "r"(saddr), "l"(gptr) : "memory")
#define CP_COMMIT() asm volatile("cp.async.commit_group;" ::: "memory")
#define CP_WAIT0()  asm volatile("cp.async.wait_group 0;" ::: "memory")

#define LDSM_X4(r0, r1, r2, r3, addr) \
    asm volatile("ldmatrix.sync.aligned.m8n8.x4.shared.b16 {%0,%1,%2,%3}, [%4];" \
        : "=r"(r0), "=r"(r1), "=r"(r2), "=r"(r3) : "r"(addr))

__device__ __forceinline__ void mma_f16(float* d, const uint32_t* a, const uint32_t* b) {
    asm volatile(
        "mma.sync.aligned.m16n8k16.row.col.f32.f16.f16.f32 "
        "{%0,%1,%2,%3}, {%4,%5,%6,%7}, {%8,%9}, {%0,%1,%2,%3};"
        : "+f"(d[0]), "+f"(d[1]), "+f"(d[2]), "+f"(d[3])
        : "r"(a[0]), "r"(a[1]), "r"(a[2]), "r"(a[3]), "r"(b[0]), "r"(b[1]));
}
__device__ __forceinline__ uint32_t packh2(float a, float b) {
    __half2 p = __floats2half2_rn(a, b);
    return *(uint32_t*)&p;
}
__device__ __forceinline__ void addh2(float& a, float& b, uint32_t p) {
    float2 f = __half22float2(*(__half2*)&p);
    a += f.x; b += f.y;
}
__device__ __forceinline__ void add8(float* f, uint4 v) {
    addh2(f[0], f[1], v.x); addh2(f[2], f[3], v.y);
    addh2(f[4], f[5], v.z); addh2(f[6], f[7], v.w);
}

// ---------------------------------------------------------------------------
// Kernel A: zero counters + W prep + x -> fp16 conversion
// ---------------------------------------------------------------------------
__global__ void prep_kernel(const float* __restrict__ x,
                            const float* __restrict__ W1,
                            const float* __restrict__ W2) {
    int i = blockIdx.x * blockDim.x + threadIdx.x;
    if (i < N_NODES * 32) {                // x: one float4 -> uint2 (4 halves)
        float4 v = ((const float4*)x)[i];
        uint2 p;
        p.x = packh2(v.x, v.y);
        p.y = packh2(v.z, v.w);
        ((uint2*)g_xh)[i] = p;
    }
    if (i < N_NODES / 4) ((int4*)g_cnt)[i] = make_int4(0, 0, 0, 0);
    if (i == 0) g_ovf_cnt = 0;
    if (i < D * D) {
        int k = i >> 7, n = i & 127;
        uint32_t so = (uint32_t)(n * RB + (k >> 3) * 16 + (k & 7) * 2);
        *(__half*)(g_Wprep + so)           = __float2half_rn(W1[i]);
        *(__half*)(g_Wprep + T_BYTES + so) = __float2half_rn(W2[i]);
    }
}

// ---------------------------------------------------------------------------
// Kernel B: bucket edges by destination (2 edges per thread)
// ---------------------------------------------------------------------------
__global__ void place_kernel(const int* __restrict__ ei) {
    int t = blockIdx.x * blockDim.x + threadIdx.x;
    #pragma unroll
    for (int u = 0; u < 2; u++) {
        int e = t * 2 + u;
        if (e >= E_EDGES) return;
        int r = ei[e];              // source
        int c = ei[E_EDGES + e];    // destination
        int p = atomicAdd(&g_cnt[c], 1);
        if (p < CAP) {
            g_list[(size_t)c * CAP + p] = r;
        } else {
            int q = atomicAdd(&g_ovf_cnt, 1);
            if (q < OVF_MAX) g_ovf[q] = make_int2(r, c);
        }
    }
}

// ---------------------------------------------------------------------------
// Kernel C: gather from fp16 x. ONE NODE PER HALF-WARP; lane owns 16B (uint4,
// 8 halves). Doubles per-warp MLP vs one-node-per-warp; LDG.128 halves the
// load instruction count. fp32 accumulation; fp16 H out in MMA layout.
// ---------------------------------------------------------------------------
__global__ void __launch_bounds__(256)
gather_kernel() {
    int g = (blockIdx.x * blockDim.x + threadIdx.x) >> 4;   // node = half-warp
    int l = threadIdx.x & 15;
    if (g >= N_NODES) return;
    int cnt0 = g_cnt[g];
    int cnt = cnt0 > CAP ? CAP : cnt0;
    const uint4* xr = (const uint4*)g_xh;    // 16 uint4 per row

    float f0[8] = {0,0,0,0,0,0,0,0};
    float f1[8] = {0,0,0,0,0,0,0,0};
    float f2[8] = {0,0,0,0,0,0,0,0};
    float f3[8] = {0,0,0,0,0,0,0,0};
    add8(f0, __ldg(&xr[(size_t)g * 16 + l]));      // own features

    int mysrc = (l < cnt) ? g_list[(size_t)g * CAP + l] : 0;
    int c2 = cnt < 16 ? cnt : 16;
    int i = 0;
    for (; i + 4 <= c2; i += 4) {
        int s0 = __shfl_sync(0xffffffffu, mysrc, i,     16);
        int s1 = __shfl_sync(0xffffffffu, mysrc, i + 1, 16);
        int s2 = __shfl_sync(0xffffffffu, mysrc, i + 2, 16);
        int s3 = __shfl_sync(0xffffffffu, mysrc, i + 3, 16);
        uint4 v0 = __ldg(&xr[(size_t)s0 * 16 + l]);
        uint4 v1 = __ldg(&xr[(size_t)s1 * 16 + l]);
        uint4 v2 = __ldg(&xr[(size_t)s2 * 16 + l]);
        uint4 v3 = __ldg(&xr[(size_t)s3 * 16 + l]);
        add8(f0, v0); add8(f1, v1); add8(f2, v2); add8(f3, v3);
    }
    for (; i < c2; i++) {
        int s = __shfl_sync(0xffffffffu, mysrc, i, 16);
        add8(f0, __ldg(&xr[(size_t)s * 16 + l]));
    }
    for (int j = 16; j < cnt; j++) {                    // rare (P ~ 3e-4)
        int s = g_list[(size_t)g * CAP + j];            // broadcast load
        add8(f1, __ldg(&xr[(size_t)s * 16 + l]));
    }
    if (cnt0 > CAP) {                                   // ultra-rare
        int n = g_ovf_cnt; if (n > OVF_MAX) n = OVF_MAX;
        for (int e = 0; e < n; e++) {
            int2 ed = g_ovf[e];
            if (ed.y == g) add8(f2, __ldg(&xr[(size_t)ed.x * 16 + l]));
        }
    }
    #pragma unroll
    for (int q = 0; q < 8; q++) f0[q] = (f0[q] + f1[q]) + (f2[q] + f3[q]);

    // store 8 halves (16B, contiguous in the swizzled layout since the 8-half
    // group starting at col l*8 maps to bytes [l*16, l*16+16) of the row)
    int t = g >> 7, row = g & 127;
    uint4 p;
    p.x = packh2(f0[0], f0[1]);
    p.y = packh2(f0[2], f0[3]);
    p.z = packh2(f0[4], f0[5]);
    p.w = packh2(f0[6], f0[7]);
    *(uint4*)(g_Hh + (size_t)t * T_BYTES + row * RB + l * 16) = p;
}

// ---------------------------------------------------------------------------
// Kernel D: persistent fp16 MLP, 512 threads (16 warps, 32x32 warp tiles),
// cp.async double-buffered A tiles.  (identical to R9)
// ---------------------------------------------------------------------------
__device__ __forceinline__ void warp_gemm(
    uint32_t sb, uint32_t a_t, uint32_t w_t,
    int m0, int n0, int lane, float acc[2][4][4])
{
    const int li = lane & 7;
    const int sub = lane >> 3;
    const uint32_t a_off = (uint32_t)((li + (sub & 1) * 8) * RB + (sub >> 1) * 16);
    const uint32_t b_off = (uint32_t)((li + (sub >> 1) * 8) * RB + (sub & 1) * 16);

    #pragma unroll
    for (int ks = 0; ks < 8; ks++) {
        const uint32_t kchunk = (uint32_t)(ks * 32);
        uint32_t ah[2][4];
        #pragma unroll
        for (int mi = 0; mi < 2; mi++) {
            uint32_t base = (uint32_t)((m0 + mi * 16) * RB) + a_off + kchunk;
            LDSM_X4(ah[mi][0], ah[mi][1], ah[mi][2], ah[mi][3], sb + a_t + base);
        }
        uint32_t bh[4][2];
        #pragma unroll
        for (int nj = 0; nj < 2; nj++) {
            uint32_t base = (uint32_t)((n0 + nj * 16) * RB) + b_off + kchunk;
            uint32_t r0, r1, r2, r3;
            LDSM_X4(r0, r1, r2, r3, sb + w_t + base);
            bh[nj * 2][0] = r0; bh[nj * 2][1] = r1;
            bh[nj * 2 + 1][0] = r2; bh[nj * 2 + 1][1] = r3;
        }
        #pragma unroll
        for (int mi = 0; mi < 2; mi++)
            #pragma unroll
            for (int ni = 0; ni < 4; ni++)
                mma_f16(acc[mi][ni], ah[mi], bh[ni]);
    }
}

__global__ void __launch_bounds__(MLP_T, 1)
mlp_mma_kernel(const float* __restrict__ b1, const float* __restrict__ b2,
               float* __restrict__ out) {
    extern __shared__ char smem[];
    const uint32_t sb = smem_u32(smem);
    const int tid = threadIdx.x;
    const int lane = tid & 31;
    const int wid = tid >> 5;
    const int m0 = (wid & 3) * 32;     // 4 m-tiles
    const int n0 = (wid >> 2) * 32;    // 4 n-tiles

    if (tid < 128) {
        ((float*)(smem + SM_B1))[tid] = b1[tid];
        ((float*)(smem + SM_B2))[tid] = b2[tid];
    }
    // stage W tiles once via cp.async
    {
        const char* wg = (const char*)g_Wprep;
        #pragma unroll 4
        for (int i = tid; i < 2 * T_BYTES / 16; i += MLP_T)
            CP_ASYNC16(sb + SM_W1 + i * 16, wg + i * 16);
    }
    // prefetch first A tile into buf0
    {
        const char* hg = (const char*)(g_Hh + (size_t)blockIdx.x * T_BYTES);
        #pragma unroll 4
        for (int i = tid; i < T_BYTES / 16; i += MLP_T)
            CP_ASYNC16(sb + SM_A0 + i * 16, hg + i * 16);
    }
    CP_COMMIT();

    int cur = 0;
    for (int t = blockIdx.x; t < NBLK; t += NSM) {
        CP_WAIT0();
        __syncthreads();                    // buf[cur] (and W on first iter) ready

        // prefetch next tile into the other buffer (overlaps with compute)
        int tn = t + NSM;
        if (tn < NBLK) {
            uint32_t dst = sb + (cur ? SM_A0 : SM_A1);
            const char* hg = (const char*)(g_Hh + (size_t)tn * T_BYTES);
            #pragma unroll 4
            for (int i = tid; i < T_BYTES / 16; i += MLP_T)
                CP_ASYNC16(dst + i * 16, hg + i * 16);
        }
        CP_COMMIT();

        const uint32_t a_t = cur ? SM_A1 : SM_A0;
        float acc[2][4][4];

        // GEMM1: H1 = relu(A @ W1 + b1)
        #pragma unroll
        for (int mi = 0; mi < 2; mi++)
            #pragma unroll
            for (int ni = 0; ni < 4; ni++)
                #pragma unroll
                for (int q = 0; q < 4; q++) acc[mi][ni][q] = 0.0f;

        warp_gemm(sb, a_t, SM_W1, m0, n0, lane, acc);
        __syncthreads();

        {
            const float* b1s = (const float*)(smem + SM_B1);
            #pragma unroll
            for (int mi = 0; mi < 2; mi++) {
                int r0 = m0 + mi * 16 + (lane >> 2);
                #pragma unroll
                for (int ni = 0; ni < 4; ni++) {
                    int c0 = n0 + ni * 8 + (lane & 3) * 2;
                    float bb0 = b1s[c0], bb1 = b1s[c0 + 1];
                    float v00 = fmaxf(acc[mi][ni][0] + bb0, 0.0f);
                    float v01 = fmaxf(acc[mi][ni][1] + bb1, 0.0f);
                    float v10 = fmaxf(acc[mi][ni][2] + bb0, 0.0f);
                    float v11 = fmaxf(acc[mi][ni][3] + bb1, 0.0f);
                    uint32_t so0 = (uint32_t)(r0 * RB + (c0 >> 3) * 16 + (c0 & 7) * 2);
                    uint32_t so1 = so0 + 8 * RB;
                    *(uint32_t*)(smem + a_t + so0) = packh2(v00, v01);
                    *(uint32_t*)(smem + a_t + so1) = packh2(v10, v11);
                }
            }
        }
        __syncthreads();

        // GEMM2: out = H1 @ W2 + b2
        #pragma unroll
        for (int mi = 0; mi < 2; mi++)
            #pragma unroll
            for (int ni = 0; ni < 4; ni++)
                #pragma unroll
                for (int q = 0; q < 4; q++) acc[mi][ni][q] = 0.0f;

        warp_gemm(sb, a_t, SM_W2, m0, n0, lane, acc);

        {
            const float* b2s = (const float*)(smem + SM_B2);
            int base_m = t * MTILE + m0;
            #pragma unroll
            for (int mi = 0; mi < 2; mi++) {
                int gr0 = base_m + mi * 16 + (lane >> 2);
                int gr1 = gr0 + 8;
                #pragma unroll
                for (int ni = 0; ni < 4; ni++) {
                    int c0 = n0 + ni * 8 + (lane & 3) * 2;
                    float bb0 = b2s[c0], bb1 = b2s[c0 + 1];
                    if (gr0 < N_NODES) {
                        float2 v = make_float2(acc[mi][ni][0] + bb0, acc[mi][ni][1] + bb1);
                        *(float2*)(out + (size_t)gr0 * D + c0) = v;
                    }
                    if (gr1 < N_NODES) {
                        float2 v = make_float2(acc[mi][ni][2] + bb0, acc[mi][ni][3] + bb1);
                        *(float2*)(out + (size_t)gr1 * D + c0) = v;
                    }
                }
            }
        }
        __syncthreads();    // done with buf[cur] before next iter overwrites A region
        cur ^= 1;
    }
}

// ---------------------------------------------------------------------------
extern "C" void kernel_launch(void* const* d_in, const int* in_sizes, int n_in,
                              void* d_out, int out_size) {
    const float* x  = (const float*)d_in[0];
    const int*   ei = (const int*)d_in[1];
    const float* W1 = (const float*)d_in[2];
    const float* b1 = (const float*)d_in[3];
    const float* W2 = (const float*)d_in[4];
    const float* b2 = (const float*)d_in[5];
    float*       out = (float*)d_out;

    prep_kernel<<<(N_NODES * 32 + 255) / 256, 256>>>(x, W1, W2);
    place_kernel<<<(E_EDGES / 2 + 255) / 256, 256>>>(ei);
    gather_kernel<<<(N_NODES * 16 + 255) / 256, 256>>>();
    {
        cudaFuncSetAttribute(mlp_mma_kernel,
                             cudaFuncAttributeMaxDynamicSharedMemorySize, SM_TOTAL);
        mlp_mma_kernel<<<NSM, MLP_T, SM_TOTAL>>>(b1, b2, out);
    }
}

// round 12
// speedup vs baseline: 1.6135x; 1.1408x over previous
#include <cuda_runtime.h>
#include <cuda_fp16.h>
#include <cstdint>

#define N_NODES 100000
#define D 128
#define E_EDGES 640000

#define MTILE 128
#define NBLK 782                 // 782 * 128 = 100096
#define NSM 148

#define CAP 40                   // in-degree capacity (Poisson(6.4): P(>40)~1e-12)
#define OVF_MAX 4096

// ---- MMA smem tile layout (row stride 272B keeps ldmatrix conflict-free) ----
#define RB 272
#define T_BYTES (128 * RB)          // 34816 per tile

// g_cnt / g_ovf_cnt are zero at first launch (static zero-init) and re-zeroed
// at the head of every mlp_mma_kernel (after gather consumed them) so each
// graph replay sees identical state.
__device__ int   g_cnt[N_NODES];
__device__ int   g_list[(size_t)N_NODES * CAP];
__device__ int   g_ovf_cnt;
__device__ int2  g_ovf[OVF_MAX];
__device__ __align__(16) __half g_xh[(size_t)N_NODES * D];     // fp16 copy of x
// H in fp16, pre-swizzled MMA layout, one T_BYTES block per 128-row tile
__device__ __align__(16) uint8_t g_Hh[(size_t)NBLK * T_BYTES];
__device__ __align__(16) uint8_t g_Wprep[2 * T_BYTES];  // fp16 W1,W2 pre-swizzled

// smem: A double buffer + W1 + W2 + biases
#define SM_A0  0
#define SM_A1  (T_BYTES)
#define SM_W1  (2 * T_BYTES)
#define SM_W2  (3 * T_BYTES)
#define SM_B1  (4 * T_BYTES)
#define SM_B2  (4 * T_BYTES + 512)
#define SM_TOTAL (4 * T_BYTES + 1024)   // 140288

#define MLP_T 512                       // 16 warps, warp tile 32x32
#define PREP_THREADS 800000             // 3.2M float4 / 4 per thread

// ---------------------------------------------------------------------------
// helpers
// ---------------------------------------------------------------------------
__device__ __forceinline__ uint32_t smem_u32(const void* p) {
    uint32_t a;
    asm("{ .reg .u64 t; cvta.to.shared.u64 t, %1; cvt.u32.u64 %0, t; }"
        : "=r"(a) : "l"(p));
    return a;
}
#define CP_ASYNC16(saddr, gptr) \
    asm volatile("cp.async.cg.shared.global [%0], [%1], 16;" \
        :: "r"(saddr), "l"(gptr) : "memory")
#define CP_COMMIT() asm volatile("cp.async.commit_group;" ::: "memory")
#define CP_WAIT0()  asm volatile("cp.async.wait_group 0;" ::: "memory")

#define LDSM_X4(r0, r1, r2, r3, addr) \
    asm volatile("ldmatrix.sync.aligned.m8n8.x4.shared.b16 {%0,%1,%2,%3}, [%4];" \
        : "=r"(r0), "=r"(r1), "=r"(r2), "=r"(r3) : "r"(addr))

__device__ __forceinline__ void mma_f16(float* d, const uint32_t* a, const uint32_t* b) {
    asm volatile(
        "mma.sync.aligned.m16n8k16.row.col.f32.f16.f16.f32 "
        "{%0,%1,%2,%3}, {%4,%5,%6,%7}, {%8,%9}, {%0,%1,%2,%3};"
        : "+f"(d[0]), "+f"(d[1]), "+f"(d[2]), "+f"(d[3])
        : "r"(a[0]), "r"(a[1]), "r"(a[2]), "r"(a[3]), "r"(b[0]), "r"(b[1]));
}
__device__ __forceinline__ uint32_t packh2(float a, float b) {
    __half2 p = __floats2half2_rn(a, b);
    return *(uint32_t*)&p;
}
__device__ __forceinline__ void addh2(float& a, float& b, uint32_t p) {
    float2 f = __half22float2(*(__half2*)&p);
    a += f.x; b += f.y;
}

// ---------------------------------------------------------------------------
// Kernel A: fused prep (x->fp16, MLP=4) + W prep + edge bucketing.
// Counters were zeroed by the previous replay's mlp kernel (or static init).
// ---------------------------------------------------------------------------
__global__ void __launch_bounds__(256)
prep_place_kernel(const float* __restrict__ x,
                  const float* __restrict__ W1,
                  const float* __restrict__ W2,
                  const int* __restrict__ ei) {
    int i = blockIdx.x * blockDim.x + threadIdx.x;

    // x conversion: 4 independent float4 loads in flight (MLP=4)
    if (i < PREP_THREADS) {
        const float4* xs = (const float4*)x;
        float4 v0 = xs[i];
        float4 v1 = xs[i + PREP_THREADS];
        float4 v2 = xs[i + 2 * PREP_THREADS];
        float4 v3 = xs[i + 3 * PREP_THREADS];
        uint2 p0, p1, p2, p3;
        p0.x = packh2(v0.x, v0.y); p0.y = packh2(v0.z, v0.w);
        p1.x = packh2(v1.x, v1.y); p1.y = packh2(v1.z, v1.w);
        p2.x = packh2(v2.x, v2.y); p2.y = packh2(v2.z, v2.w);
        p3.x = packh2(v3.x, v3.y); p3.y = packh2(v3.z, v3.w);
        uint2* xd = (uint2*)g_xh;
        xd[i] = p0;
        xd[i + PREP_THREADS] = p1;
        xd[i + 2 * PREP_THREADS] = p2;
        xd[i + 3 * PREP_THREADS] = p3;
    }
    // weight prep
    if (i < D * D) {
        int k = i >> 7, n = i & 127;
        uint32_t so = (uint32_t)(n * RB + (k >> 3) * 16 + (k & 7) * 2);
        *(__half*)(g_Wprep + so)           = __float2half_rn(W1[i]);
        *(__half*)(g_Wprep + T_BYTES + so) = __float2half_rn(W2[i]);
    }
    // edge bucketing: 2 edges per thread
    if (i < E_EDGES / 2) {
        #pragma unroll
        for (int u = 0; u < 2; u++) {
            int e = i * 2 + u;
            int r = ei[e];              // source
            int c = ei[E_EDGES + e];    // destination
            int p = atomicAdd(&g_cnt[c], 1);
            if (p < CAP) {
                g_list[(size_t)c * CAP + p] = r;
            } else {
                int q = atomicAdd(&g_ovf_cnt, 1);
                if (q < OVF_MAX) g_ovf[q] = make_int2(r, c);
            }
        }
    }
}

// ---------------------------------------------------------------------------
// Kernel B: gather from fp16 x. One warp per node; lane owns 4 dims (8B).
// fp32 accumulation; writes fp16 H in swizzled MMA layout.  (R9-proven)
// ---------------------------------------------------------------------------
__global__ void __launch_bounds__(256)
gather_kernel() {
    int gw = (blockIdx.x * blockDim.x + threadIdx.x) >> 5;
    int lane = threadIdx.x & 31;
    if (gw >= N_NODES) return;
    int cnt0 = g_cnt[gw];
    int cnt = cnt0 > CAP ? CAP : cnt0;
    const uint2* xr = (const uint2*)g_xh;    // 32 uint2 per row

    uint2 own = __ldg(&xr[(size_t)gw * 32 + lane]);
    float ax0 = 0.f, ay0 = 0.f, az0 = 0.f, aw0 = 0.f;
    float ax1 = 0.f, ay1 = 0.f, az1 = 0.f, aw1 = 0.f;
    float ax2 = 0.f, ay2 = 0.f, az2 = 0.f, aw2 = 0.f;
    float ax3 = 0.f, ay3 = 0.f, az3 = 0.f, aw3 = 0.f;
    addh2(ax0, ay0, own.x); addh2(az0, aw0, own.y);

    int mysrc = (lane < cnt) ? g_list[(size_t)gw * CAP + lane] : 0;
    int c2 = cnt < 32 ? cnt : 32;
    int i = 0;
    for (; i + 4 <= c2; i += 4) {
        int s0 = __shfl_sync(0xffffffffu, mysrc, i);
        int s1 = __shfl_sync(0xffffffffu, mysrc, i + 1);
        int s2 = __shfl_sync(0xffffffffu, mysrc, i + 2);
        int s3 = __shfl_sync(0xffffffffu, mysrc, i + 3);
        uint2 v0 = __ldg(&xr[(size_t)s0 * 32 + lane]);
        uint2 v1 = __ldg(&xr[(size_t)s1 * 32 + lane]);
        uint2 v2 = __ldg(&xr[(size_t)s2 * 32 + lane]);
        uint2 v3 = __ldg(&xr[(size_t)s3 * 32 + lane]);
        addh2(ax0, ay0, v0.x); addh2(az0, aw0, v0.y);
        addh2(ax1, ay1, v1.x); addh2(az1, aw1, v1.y);
        addh2(ax2, ay2, v2.x); addh2(az2, aw2, v2.y);
        addh2(ax3, ay3, v3.x); addh2(az3, aw3, v3.y);
    }
    for (; i < c2; i++) {
        int s = __shfl_sync(0xffffffffu, mysrc, i);
        uint2 v = __ldg(&xr[(size_t)s * 32 + lane]);
        addh2(ax0, ay0, v.x); addh2(az0, aw0, v.y);
    }
    for (int j = 32; j < cnt; j++) {                    // rare
        int s = g_list[(size_t)gw * CAP + j];
        uint2 v = __ldg(&xr[(size_t)s * 32 + lane]);
        addh2(ax0, ay0, v.x); addh2(az0, aw0, v.y);
    }
    if (cnt0 > CAP) {                                   // ultra-rare
        int n = g_ovf_cnt; if (n > OVF_MAX) n = OVF_MAX;
        for (int e = 0; e < n; e++) {
            int2 ed = g_ovf[e];
            if (ed.y == gw) {
                uint2 v = __ldg(&xr[(size_t)ed.x * 32 + lane]);
                addh2(ax0, ay0, v.x); addh2(az0, aw0, v.y);
            }
        }
    }
    float fx = (ax0 + ax1) + (ax2 + ax3);
    float fy = (ay0 + ay1) + (ay2 + ay3);
    float fz = (az0 + az1) + (az2 + az3);
    float fw = (aw0 + aw1) + (aw2 + aw3);

    int t = gw >> 7, row = gw & 127;
    uint32_t so = (uint32_t)(row * RB + (lane >> 1) * 16 + (lane & 1) * 8);
    uint2 p;
    p.x = packh2(fx, fy);
    p.y = packh2(fz, fw);
    *(uint2*)(g_Hh + (size_t)t * T_BYTES + so) = p;
}

// ---------------------------------------------------------------------------
// Kernel C: persistent fp16 MLP + counter re-zero for the next replay.
// ---------------------------------------------------------------------------
__device__ __forceinline__ void warp_gemm(
    uint32_t sb, uint32_t a_t, uint32_t w_t,
    int m0, int n0, int lane, float acc[2][4][4])
{
    const int li = lane & 7;
    const int sub = lane >> 3;
    const uint32_t a_off = (uint32_t)((li + (sub & 1) * 8) * RB + (sub >> 1) * 16);
    const uint32_t b_off = (uint32_t)((li + (sub >> 1) * 8) * RB + (sub & 1) * 16);

    #pragma unroll
    for (int ks = 0; ks < 8; ks++) {
        const uint32_t kchunk = (uint32_t)(ks * 32);
        uint32_t ah[2][4];
        #pragma unroll
        for (int mi = 0; mi < 2; mi++) {
            uint32_t base = (uint32_t)((m0 + mi * 16) * RB) + a_off + kchunk;
            LDSM_X4(ah[mi][0], ah[mi][1], ah[mi][2], ah[mi][3], sb + a_t + base);
        }
        uint32_t bh[4][2];
        #pragma unroll
        for (int nj = 0; nj < 2; nj++) {
            uint32_t base = (uint32_t)((n0 + nj * 16) * RB) + b_off + kchunk;
            uint32_t r0, r1, r2, r3;
            LDSM_X4(r0, r1, r2, r3, sb + w_t + base);
            bh[nj * 2][0] = r0; bh[nj * 2][1] = r1;
            bh[nj * 2 + 1][0] = r2; bh[nj * 2 + 1][1] = r3;
        }
        #pragma unroll
        for (int mi = 0; mi < 2; mi++)
            #pragma unroll
            for (int ni = 0; ni < 4; ni++)
                mma_f16(acc[mi][ni], ah[mi], bh[ni]);
    }
}

__global__ void __launch_bounds__(MLP_T, 1)
mlp_mma_kernel(const float* __restrict__ b1, const float* __restrict__ b2,
               float* __restrict__ out) {
    extern __shared__ char smem[];
    const uint32_t sb = smem_u32(smem);
    const int tid = threadIdx.x;
    const int lane = tid & 31;
    const int wid = tid >> 5;
    const int m0 = (wid & 3) * 32;     // 4 m-tiles
    const int n0 = (wid >> 2) * 32;    // 4 n-tiles

    // stage W tiles once via cp.async (async; overlaps the zeroing below)
    {
        const char* wg = (const char*)g_Wprep;
        #pragma unroll 4
        for (int i = tid; i < 2 * T_BYTES / 16; i += MLP_T)
            CP_ASYNC16(sb + SM_W1 + i * 16, wg + i * 16);
    }
    // prefetch first A tile into buf0
    {
        const char* hg = (const char*)(g_Hh + (size_t)blockIdx.x * T_BYTES);
        #pragma unroll 4
        for (int i = tid; i < T_BYTES / 16; i += MLP_T)
            CP_ASYNC16(sb + SM_A0 + i * 16, hg + i * 16);
    }
    CP_COMMIT();

    // re-zero counters for the next graph replay (gather already consumed them)
    {
        int gt = blockIdx.x * MLP_T + tid;               // 75776 threads
        int4* c4 = (int4*)g_cnt;
        for (int i = gt; i < N_NODES / 4; i += NSM * MLP_T)
            c4[i] = make_int4(0, 0, 0, 0);
        if (gt == 0) g_ovf_cnt = 0;
    }

    if (tid < 128) {
        ((float*)(smem + SM_B1))[tid] = b1[tid];
        ((float*)(smem + SM_B2))[tid] = b2[tid];
    }

    int cur = 0;
    for (int t = blockIdx.x; t < NBLK; t += NSM) {
        CP_WAIT0();
        __syncthreads();                    // buf[cur] (and W on first iter) ready

        // prefetch next tile into the other buffer (overlaps with compute)
        int tn = t + NSM;
        if (tn < NBLK) {
            uint32_t dst = sb + (cur ? SM_A0 : SM_A1);
            const char* hg = (const char*)(g_Hh + (size_t)tn * T_BYTES);
            #pragma unroll 4
            for (int i = tid; i < T_BYTES / 16; i += MLP_T)
                CP_ASYNC16(dst + i * 16, hg + i * 16);
        }
        CP_COMMIT();

        const uint32_t a_t = cur ? SM_A1 : SM_A0;
        float acc[2][4][4];

        // GEMM1: H1 = relu(A @ W1 + b1)
        #pragma unroll
        for (int mi = 0; mi < 2; mi++)
            #pragma unroll
            for (int ni = 0; ni < 4; ni++)
                #pragma unroll
                for (int q = 0; q < 4; q++) acc[mi][ni][q] = 0.0f;

        warp_gemm(sb, a_t, SM_W1, m0, n0, lane, acc);
        __syncthreads();

        {
            const float* b1s = (const float*)(smem + SM_B1);
            #pragma unroll
            for (int mi = 0; mi < 2; mi++) {
                int r0 = m0 + mi * 16 + (lane >> 2);
                #pragma unroll
                for (int ni = 0; ni < 4; ni++) {
                    int c0 = n0 + ni * 8 + (lane & 3) * 2;
                    float bb0 = b1s[c0], bb1 = b1s[c0 + 1];
                    float v00 = fmaxf(acc[mi][ni][0] + bb0, 0.0f);
                    float v01 = fmaxf(acc[mi][ni][1] + bb1, 0.0f);
                    float v10 = fmaxf(acc[mi][ni][2] + bb0, 0.0f);
                    float v11 = fmaxf(acc[mi][ni][3] + bb1, 0.0f);
                    uint32_t so0 = (uint32_t)(r0 * RB + (c0 >> 3) * 16 + (c0 & 7) * 2);
                    uint32_t so1 = so0 + 8 * RB;
                    *(uint32_t*)(smem + a_t + so0) = packh2(v00, v01);
                    *(uint32_t*)(smem + a_t + so1) = packh2(v10, v11);
                }
            }
        }
        __syncthreads();

        // GEMM2: out = H1 @ W2 + b2
        #pragma unroll
        for (int mi = 0; mi < 2; mi++)
            #pragma unroll
            for (int ni = 0; ni < 4; ni++)
                #pragma unroll
                for (int q = 0; q < 4; q++) acc[mi][ni][q] = 0.0f;

        warp_gemm(sb, a_t, SM_W2, m0, n0, lane, acc);

        {
            const float* b2s = (const float*)(smem + SM_B2);
            int base_m = t * MTILE + m0;
            #pragma unroll
            for (int mi = 0; mi < 2; mi++) {
                int gr0 = base_m + mi * 16 + (lane >> 2);
                int gr1 = gr0 + 8;
                #pragma unroll
                for (int ni = 0; ni < 4; ni++) {
                    int c0 = n0 + ni * 8 + (lane & 3) * 2;
                    float bb0 = b2s[c0], bb1 = b2s[c0 + 1];
                    if (gr0 < N_NODES) {
                        float2 v = make_float2(acc[mi][ni][0] + bb0, acc[mi][ni][1] + bb1);
                        *(float2*)(out + (size_t)gr0 * D + c0) = v;
                    }
                    if (gr1 < N_NODES) {
                        float2 v = make_float2(acc[mi][ni][2] + bb0, acc[mi][ni][3] + bb1);
                        *(float2*)(out + (size_t)gr1 * D + c0) = v;
                    }
                }
            }
        }
        __syncthreads();    // done with buf[cur] before next iter overwrites A region
        cur ^= 1;
    }
}

// ---------------------------------------------------------------------------
extern "C" void kernel_launch(void* const* d_in, const int* in_sizes, int n_in,
                              void* d_out, int out_size) {
    const float* x  = (const float*)d_in[0];
    const int*   ei = (const int*)d_in[1];
    const float* W1 = (const float*)d_in[2];
    const float* b1 = (const float*)d_in[3];
    const float* W2 = (const float*)d_in[4];
    const float* b2 = (const float*)d_in[5];
    float*       out = (float*)d_out;

    prep_place_kernel<<<PREP_THREADS / 256, 256>>>(x, W1, W2, ei);
    gather_kernel<<<(N_NODES * 32 + 255) / 256, 256>>>();
    {
        cudaFuncSetAttribute(mlp_mma_kernel,
                             cudaFuncAttributeMaxDynamicSharedMemorySize, SM_TOTAL);
        mlp_mma_kernel<<<NSM, MLP_T, SM_TOTAL>>>(b1, b2, out);
    }
}

// round 13
// speedup vs baseline: 1.6531x; 1.0245x over previous
#include <cuda_runtime.h>
#include <cuda_fp16.h>
#include <cstdint>

#define N_NODES 100000
#define D 128
#define E_EDGES 640000

#define MTILE 128
#define NBLK 782                 // 782 * 128 = 100096
#define NSM 148

#define CAP 40
#define OVF_MAX 4096

#define RB 272
#define T_BYTES (128 * RB)          // 34816 per tile

__device__ int   g_cnt[N_NODES];     // zeroed by previous replay's MLP kernel
__device__ int   g_list[(size_t)N_NODES * CAP];
__device__ int   g_ovf_cnt;
__device__ int2  g_ovf[OVF_MAX];
__device__ __align__(16) __half g_xh[(size_t)N_NODES * D];
__device__ __align__(16) uint8_t g_Hh[(size_t)NBLK * T_BYTES];
__device__ __align__(16) uint8_t g_Wprep[2 * T_BYTES];

#define SM_A0  0
#define SM_A1  (T_BYTES)
#define SM_W1  (2 * T_BYTES)
#define SM_W2  (3 * T_BYTES)
#define SM_B1  (4 * T_BYTES)
#define SM_B2  (4 * T_BYTES + 512)
#define SM_TOTAL (4 * T_BYTES + 1024)   // 140288

#define MLP_T 256                       // 8 warps, warp tile 16m x 128n
#define PREP_T 400000                   // x-convert threads (8 float4 each)

// ---------------------------------------------------------------------------
__device__ __forceinline__ uint32_t smem_u32(const void* p) {
    uint32_t a;
    asm("{ .reg .u64 t; cvta.to.shared.u64 t, %1; cvt.u32.u64 %0, t; }"
        : "=r"(a) : "l"(p));
    return a;
}
#define CP_ASYNC16(saddr, gptr) \
    asm volatile("cp.async.cg.shared.global [%0], [%1], 16;" \
        :: "r"(saddr), "l"(gptr) : "memory")
#define CP_COMMIT() asm volatile("cp.async.commit_group;" ::: "memory")
#define CP_WAIT0()  asm volatile("cp.async.wait_group 0;" ::: "memory")

#define LDSM_X4(r0, r1, r2, r3, addr) \
    asm volatile("ldmatrix.sync.aligned.m8n8.x4.shared.b16 {%0,%1,%2,%3}, [%4];" \
        : "=r"(r0), "=r"(r1), "=r"(r2), "=r"(r3) : "r"(addr))

__device__ __forceinline__ void mma_f16(float* d, const uint32_t* a,
                                        uint32_t b0, uint32_t b1) {
    asm volatile(
        "mma.sync.aligned.m16n8k16.row.col.f32.f16.f16.f32 "
        "{%0,%1,%2,%3}, {%4,%5,%6,%7}, {%8,%9}, {%0,%1,%2,%3};"
        : "+f"(d[0]), "+f"(d[1]), "+f"(d[2]), "+f"(d[3])
        : "r"(a[0]), "r"(a[1]), "r"(a[2]), "r"(a[3]), "r"(b0), "r"(b1));
}
__device__ __forceinline__ uint32_t packh2(float a, float b) {
    __half2 p = __floats2half2_rn(a, b);
    return *(uint32_t*)&p;
}
__device__ __forceinline__ void addh2(float& a, float& b, uint32_t p) {
    float2 f = __half22float2(*(__half2*)&p);
    a += f.x; b += f.y;
}

// ---------------------------------------------------------------------------
// Kernel A: fused prep (x->fp16, 8 loads in flight) + W prep + edge bucketing
// (4 edges per thread, int4-batched index loads).
// ---------------------------------------------------------------------------
__global__ void __launch_bounds__(256)
prep_place_kernel(const float* __restrict__ x,
                  const float* __restrict__ W1,
                  const float* __restrict__ W2,
                  const int* __restrict__ ei) {
    int i = blockIdx.x * blockDim.x + threadIdx.x;

    if (i < PREP_T) {
        const float4* xs = (const float4*)x;
        float4 v[8];
        #pragma unroll
        for (int q = 0; q < 4; q++) {
            v[2 * q]     = xs[q * 2 * PREP_T + 2 * i];
            v[2 * q + 1] = xs[q * 2 * PREP_T + 2 * i + 1];
        }
        uint4* xd = (uint4*)g_xh;
        #pragma unroll
        for (int q = 0; q < 4; q++) {
            uint4 p;
            p.x = packh2(v[2 * q].x,     v[2 * q].y);
            p.y = packh2(v[2 * q].z,     v[2 * q].w);
            p.z = packh2(v[2 * q + 1].x, v[2 * q + 1].y);
            p.w = packh2(v[2 * q + 1].z, v[2 * q + 1].w);
            xd[q * PREP_T + i] = p;
        }
    }
    if (i < D * D) {
        int k = i >> 7, n = i & 127;
        uint32_t so = (uint32_t)(n * RB + (k >> 3) * 16 + (k & 7) * 2);
        *(__half*)(g_Wprep + so)           = __float2half_rn(W1[i]);
        *(__half*)(g_Wprep + T_BYTES + so) = __float2half_rn(W2[i]);
    }
    if (i < E_EDGES / 4) {
        int4 rr = *(const int4*)(ei + 4 * i);             // sources
        int4 cc = *(const int4*)(ei + E_EDGES + 4 * i);   // destinations
        int r[4] = {rr.x, rr.y, rr.z, rr.w};
        int c[4] = {cc.x, cc.y, cc.z, cc.w};
        #pragma unroll
        for (int u = 0; u < 4; u++) {
            int p = atomicAdd(&g_cnt[c[u]], 1);
            if (p < CAP) {
                g_list[(size_t)c[u] * CAP + p] = r[u];
            } else {
                int q = atomicAdd(&g_ovf_cnt, 1);
                if (q < OVF_MAX) g_ovf[q] = make_int2(r[u], c[u]);
            }
        }
    }
}

// ---------------------------------------------------------------------------
// Kernel B: gather (R9-proven form, byte-identical)
// ---------------------------------------------------------------------------
__global__ void __launch_bounds__(256)
gather_kernel() {
    int gw = (blockIdx.x * blockDim.x + threadIdx.x) >> 5;
    int lane = threadIdx.x & 31;
    if (gw >= N_NODES) return;
    int cnt0 = g_cnt[gw];
    int cnt = cnt0 > CAP ? CAP : cnt0;
    const uint2* xr = (const uint2*)g_xh;

    uint2 own = __ldg(&xr[(size_t)gw * 32 + lane]);
    float ax0 = 0.f, ay0 = 0.f, az0 = 0.f, aw0 = 0.f;
    float ax1 = 0.f, ay1 = 0.f, az1 = 0.f, aw1 = 0.f;
    float ax2 = 0.f, ay2 = 0.f, az2 = 0.f, aw2 = 0.f;
    float ax3 = 0.f, ay3 = 0.f, az3 = 0.f, aw3 = 0.f;
    addh2(ax0, ay0, own.x); addh2(az0, aw0, own.y);

    int mysrc = (lane < cnt) ? g_list[(size_t)gw * CAP + lane] : 0;
    int c2 = cnt < 32 ? cnt : 32;
    int i = 0;
    for (; i + 4 <= c2; i += 4) {
        int s0 = __shfl_sync(0xffffffffu, mysrc, i);
        int s1 = __shfl_sync(0xffffffffu, mysrc, i + 1);
        int s2 = __shfl_sync(0xffffffffu, mysrc, i + 2);
        int s3 = __shfl_sync(0xffffffffu, mysrc, i + 3);
        uint2 v0 = __ldg(&xr[(size_t)s0 * 32 + lane]);
        uint2 v1 = __ldg(&xr[(size_t)s1 * 32 + lane]);
        uint2 v2 = __ldg(&xr[(size_t)s2 * 32 + lane]);
        uint2 v3 = __ldg(&xr[(size_t)s3 * 32 + lane]);
        addh2(ax0, ay0, v0.x); addh2(az0, aw0, v0.y);
        addh2(ax1, ay1, v1.x); addh2(az1, aw1, v1.y);
        addh2(ax2, ay2, v2.x); addh2(az2, aw2, v2.y);
        addh2(ax3, ay3, v3.x); addh2(az3, aw3, v3.y);
    }
    for (; i < c2; i++) {
        int s = __shfl_sync(0xffffffffu, mysrc, i);
        uint2 v = __ldg(&xr[(size_t)s * 32 + lane]);
        addh2(ax0, ay0, v.x); addh2(az0, aw0, v.y);
    }
    for (int j = 32; j < cnt; j++) {
        int s = g_list[(size_t)gw * CAP + j];
        uint2 v = __ldg(&xr[(size_t)s * 32 + lane]);
        addh2(ax0, ay0, v.x); addh2(az0, aw0, v.y);
    }
    if (cnt0 > CAP) {
        int n = g_ovf_cnt; if (n > OVF_MAX) n = OVF_MAX;
        for (int e = 0; e < n; e++) {
            int2 ed = g_ovf[e];
            if (ed.y == gw) {
                uint2 v = __ldg(&xr[(size_t)ed.x * 32 + lane]);
                addh2(ax0, ay0, v.x); addh2(az0, aw0, v.y);
            }
        }
    }
    float fx = (ax0 + ax1) + (ax2 + ax3);
    float fy = (ay0 + ay1) + (ay2 + ay3);
    float fz = (az0 + az1) + (az2 + az3);
    float fw = (aw0 + aw1) + (aw2 + aw3);

    int t = gw >> 7, row = gw & 127;
    uint32_t so = (uint32_t)(row * RB + (lane >> 1) * 16 + (lane & 1) * 8);
    uint2 p;
    p.x = packh2(fx, fy);
    p.y = packh2(fz, fw);
    *(uint2*)(g_Hh + (size_t)t * T_BYTES + so) = p;
}

// ---------------------------------------------------------------------------
// Kernel C: persistent fp16 MLP, 8 warps, warp tile m16 x n128.
// GEMM1 acc (C-fragment) is converted IN REGISTERS to GEMM2's A-fragment
// (c0,c1 / c2,c3 of n-tiles 2j,2j+1 -> a0..a3 of k-step j): no H1 smem
// round-trip, one __syncthreads per tile.
// ---------------------------------------------------------------------------
__global__ void __launch_bounds__(MLP_T, 1)
mlp_mma_kernel(const float* __restrict__ b1, const float* __restrict__ b2,
               float* __restrict__ out) {
    extern __shared__ char smem[];
    const uint32_t sb = smem_u32(smem);
    const int tid = threadIdx.x;
    const int lane = tid & 31;
    const int wid = tid >> 5;          // 0..7
    const int m0 = wid * 16;

    // stage W tiles + first A tile via cp.async
    {
        const char* wg = (const char*)g_Wprep;
        #pragma unroll 4
        for (int i = tid; i < 2 * T_BYTES / 16; i += MLP_T)
            CP_ASYNC16(sb + SM_W1 + i * 16, wg + i * 16);
        const char* hg = (const char*)(g_Hh + (size_t)blockIdx.x * T_BYTES);
        #pragma unroll 4
        for (int i = tid; i < T_BYTES / 16; i += MLP_T)
            CP_ASYNC16(sb + SM_A0 + i * 16, hg + i * 16);
    }
    CP_COMMIT();

    // re-zero counters for the next graph replay
    {
        int gt = blockIdx.x * MLP_T + tid;
        int4* c4 = (int4*)g_cnt;
        for (int i = gt; i < N_NODES / 4; i += NSM * MLP_T)
            c4[i] = make_int4(0, 0, 0, 0);
        if (gt == 0) g_ovf_cnt = 0;
    }
    if (tid < 128) {
        ((float*)(smem + SM_B1))[tid] = b1[tid];
        ((float*)(smem + SM_B2))[tid] = b2[tid];
    }

    const int li = lane & 7;
    const int sub = lane >> 3;
    // A-frag addr (rows m0 + li + (sub&1)*8, k-bytes (sub>>1)*16)
    const uint32_t a_off = (uint32_t)((m0 + li + (sub & 1) * 8) * RB + (sub >> 1) * 16);
    // B-frag addr (rows li + (sub>>1)*8 within n-tile, k-bytes (sub&1)*16)
    const uint32_t b_off = (uint32_t)((li + (sub >> 1) * 8) * RB + (sub & 1) * 16);
    const int cbase = 2 * (lane & 3);
    const int gid = lane >> 2;

    int cur = 0;
    for (int t = blockIdx.x; t < NBLK; t += NSM) {
        CP_WAIT0();
        __syncthreads();                 // buf[cur] (+W first iter) ready; prev tile done

        int tn = t + NSM;
        if (tn < NBLK) {
            uint32_t dst = sb + (cur ? SM_A0 : SM_A1);
            const char* hg = (const char*)(g_Hh + (size_t)tn * T_BYTES);
            #pragma unroll 4
            for (int i = tid; i < T_BYTES / 16; i += MLP_T)
                CP_ASYNC16(dst + i * 16, hg + i * 16);
        }
        CP_COMMIT();

        const uint32_t a_t = cur ? SM_A1 : SM_A0;
        float acc[16][4];
        #pragma unroll
        for (int ni = 0; ni < 16; ni++)
            #pragma unroll
            for (int q = 0; q < 4; q++) acc[ni][q] = 0.0f;

        // ---- GEMM1: acc = A @ W1 over K=128, n = 0..127 ----
        #pragma unroll
        for (int ks = 0; ks < 8; ks++) {
            uint32_t ah[4];
            LDSM_X4(ah[0], ah[1], ah[2], ah[3], sb + a_t + a_off + ks * 32);
            #pragma unroll
            for (int nj = 0; nj < 8; nj++) {
                uint32_t r0, r1, r2, r3;
                LDSM_X4(r0, r1, r2, r3,
                        sb + SM_W1 + b_off + (uint32_t)(nj * 16 * RB) + ks * 32);
                mma_f16(acc[2 * nj],     ah, r0, r1);
                mma_f16(acc[2 * nj + 1], ah, r2, r3);
            }
        }

        // ---- epilogue1 in registers: relu(+b1), convert C-frag -> A-frag ----
        uint32_t af[8][4];
        {
            const float* b1s = (const float*)(smem + SM_B1);
            #pragma unroll
            for (int ni = 0; ni < 16; ni++) {
                float2 bb = *(const float2*)(b1s + ni * 8 + cbase);
                acc[ni][0] = fmaxf(acc[ni][0] + bb.x, 0.0f);
                acc[ni][1] = fmaxf(acc[ni][1] + bb.y, 0.0f);
                acc[ni][2] = fmaxf(acc[ni][2] + bb.x, 0.0f);
                acc[ni][3] = fmaxf(acc[ni][3] + bb.y, 0.0f);
            }
            #pragma unroll
            for (int j = 0; j < 8; j++) {
                af[j][0] = packh2(acc[2 * j][0],     acc[2 * j][1]);
                af[j][1] = packh2(acc[2 * j][2],     acc[2 * j][3]);
                af[j][2] = packh2(acc[2 * j + 1][0], acc[2 * j + 1][1]);
                af[j][3] = packh2(acc[2 * j + 1][2], acc[2 * j + 1][3]);
            }
        }

        #pragma unroll
        for (int ni = 0; ni < 16; ni++)
            #pragma unroll
            for (int q = 0; q < 4; q++) acc[ni][q] = 0.0f;

        // ---- GEMM2: acc = H1 @ W2, A from registers ----
        #pragma unroll
        for (int j = 0; j < 8; j++) {
            #pragma unroll
            for (int nj = 0; nj < 8; nj++) {
                uint32_t r0, r1, r2, r3;
                LDSM_X4(r0, r1, r2, r3,
                        sb + SM_W2 + b_off + (uint32_t)(nj * 16 * RB) + j * 32);
                mma_f16(acc[2 * nj],     af[j], r0, r1);
                mma_f16(acc[2 * nj + 1], af[j], r2, r3);
            }
        }

        // ---- epilogue2: +b2, store ----
        {
            const float* b2s = (const float*)(smem + SM_B2);
            int gr0 = t * MTILE + m0 + gid;
            int gr1 = gr0 + 8;
            #pragma unroll
            for (int ni = 0; ni < 16; ni++) {
                int c0 = ni * 8 + cbase;
                float2 bb = *(const float2*)(b2s + c0);
                if (gr0 < N_NODES) {
                    float2 v = make_float2(acc[ni][0] + bb.x, acc[ni][1] + bb.y);
                    *(float2*)(out + (size_t)gr0 * D + c0) = v;
                }
                if (gr1 < N_NODES) {
                    float2 v = make_float2(acc[ni][2] + bb.x, acc[ni][3] + bb.y);
                    *(float2*)(out + (size_t)gr1 * D + c0) = v;
                }
            }
        }
        cur ^= 1;
    }
}

// ---------------------------------------------------------------------------
extern "C" void kernel_launch(void* const* d_in, const int* in_sizes, int n_in,
                              void* d_out, int out_size) {
    const float* x  = (const float*)d_in[0];
    const int*   ei = (const int*)d_in[1];
    const float* W1 = (const float*)d_in[2];
    const float* b1 = (const float*)d_in[3];
    const float* W2 = (const float*)d_in[4];
    const float* b2 = (const float*)d_in[5];
    float*       out = (float*)d_out;

    prep_place_kernel<<<(PREP_T + 255) / 256, 256>>>(x, W1, W2, ei);
    gather_kernel<<<(N_NODES * 32 + 255) / 256, 256>>>();
    {
        cudaFuncSetAttribute(mlp_mma_kernel,
                             cudaFuncAttributeMaxDynamicSharedMemorySize, SM_TOTAL);
        mlp_mma_kernel<<<NSM, MLP_T, SM_TOTAL>>>(b1, b2, out);
    }
}